// round 10
// baseline (speedup 1.0000x reference)
#include <cuda_runtime.h>
#include <cuda_bf16.h>

#define N_NODES 50000
#define E_EDGES 600000
#define FDIM    128
#define HDIM    16

// scratch — device symbols referenced ONLY inside device code.
// Self-cleaning: scan_kernel resets g_degi; offsets/cursors recomputed each replay.
__device__ int   g_mode;
__device__ int   g_degi  [N_NODES];          // 0 at rest
__device__ int   g_off   [N_NODES + 1];
__device__ int   g_cursor[N_NODES];
__device__ int   g_csr   [E_EDGES];          // source node per incoming edge, bucketed by dest
__device__ float g_dinv  [N_NODES];
__device__ float g_h     [N_NODES * HDIM];   // h1s = dinv*(x@W1)
__device__ float g_h2    [N_NODES * HDIM];   // z1s = dinv*relu(...)
__device__ float g_a     [N_NODES * HDIM];   // pre-GEMM features for final layer

__device__ __forceinline__ int load_edge_idx(const unsigned int* __restrict__ ei,
                                             int mode, int pos) {
    if (mode == 1) return (int)ei[2 * pos];             // int64: low word
    unsigned int v = ei[pos];
    if (mode == 2) return (int)__int_as_float((int)v);  // float32-encoded
    return (int)v;                                      // int32
}

// ---- launch 0: detect edge dtype (1 block) ----
__global__ void detect_kernel(const unsigned int* __restrict__ w) {
    __shared__ int s_big, s_oddnz;
    if (threadIdx.x == 0) { s_big = 0; s_oddnz = 0; }
    __syncthreads();
    int big = 0, oddnz = 0;
    for (int k = threadIdx.x; k < 4096; k += blockDim.x) {
        unsigned int v = w[k];
        if (v >= 0x30000000u) big++;
        if ((k & 1) && v != 0u) oddnz++;
    }
    if (big)   atomicAdd(&s_big, big);
    if (oddnz) atomicAdd(&s_oddnz, oddnz);
    __syncthreads();
    if (threadIdx.x == 0) {
        if (s_big > 1024)      g_mode = 2;
        else if (s_oddnz == 0) g_mode = 1;
        else                   g_mode = 0;
    }
}

// ---- launch 1: integer in-degree count ----
__global__ void deg_kernel(const unsigned int* __restrict__ ei) {
    int e = blockIdx.x * blockDim.x + threadIdx.x;
    if (e < E_EDGES) {
        int c = load_edge_idx(ei, g_mode, E_EDGES + e);
        if (c >= 0 && c < N_NODES)
            atomicAdd(&g_degi[c], 1);
    }
}

// ---- launch 2: single-block exclusive scan -> offsets, cursors, dinv; reset degi ----
__global__ void scan_kernel() {
    __shared__ int warp_sums[32];
    __shared__ int chunk_base;
    if (threadIdx.x == 0) chunk_base = 0;
    __syncthreads();

    int lane = threadIdx.x & 31;
    int wid  = threadIdx.x >> 5;

    for (int base = 0; base < N_NODES; base += 1024) {
        int i = base + (int)threadIdx.x;
        int v = (i < N_NODES) ? g_degi[i] : 0;

        // inclusive warp scan
        int s = v;
#pragma unroll
        for (int o = 1; o < 32; o <<= 1) {
            int t = __shfl_up_sync(0xFFFFFFFFu, s, o);
            if (lane >= o) s += t;
        }
        if (lane == 31) warp_sums[wid] = s;
        __syncthreads();
        if (wid == 0) {
            int ws = warp_sums[lane];
#pragma unroll
            for (int o = 1; o < 32; o <<= 1) {
                int t = __shfl_up_sync(0xFFFFFFFFu, ws, o);
                if (lane >= o) ws += t;
            }
            warp_sums[lane] = ws;
        }
        __syncthreads();

        int excl = s - v + (wid > 0 ? warp_sums[wid - 1] : 0) + chunk_base;
        if (i < N_NODES) {
            g_off[i]    = excl;
            g_cursor[i] = excl;
            g_dinv[i]   = rsqrtf((float)v + 1.0f);  // +1 self-loop
            g_degi[i]   = 0;                         // self-clean
        }
        __syncthreads();
        if (threadIdx.x == 0) chunk_base += warp_sums[31];
        __syncthreads();
    }
    if (threadIdx.x == 0) g_off[N_NODES] = chunk_base;
}

// ---- launch 3: h1s = dinv * (x @ W1) ----
__global__ void gemm1_kernel(const float* __restrict__ x, const float* __restrict__ W1) {
    __shared__ float sW1[FDIM * HDIM];
    for (int i = threadIdx.x; i < FDIM * HDIM; i += blockDim.x)
        sW1[i] = W1[i];
    __syncthreads();

    int idx = blockIdx.x * blockDim.x + threadIdx.x;
    if (idx >= N_NODES * HDIM) return;
    int row = idx >> 4;
    int j   = idx & 15;

    const float4* xr = (const float4*)(x + (size_t)row * FDIM);
    float acc = 0.0f;
#pragma unroll
    for (int k4 = 0; k4 < FDIM / 4; k4++) {
        float4 xv = xr[k4];
        acc += xv.x * sW1[(k4 * 4 + 0) * HDIM + j];
        acc += xv.y * sW1[(k4 * 4 + 1) * HDIM + j];
        acc += xv.z * sW1[(k4 * 4 + 2) * HDIM + j];
        acc += xv.w * sW1[(k4 * 4 + 3) * HDIM + j];
    }
    g_h[idx] = acc * g_dinv[row];
}

// ---- launch 4: bucket-fill CSR (dest-grouped source lists) ----
__global__ void fill_kernel(const unsigned int* __restrict__ ei) {
    int e = blockIdx.x * blockDim.x + threadIdx.x;
    if (e >= E_EDGES) return;
    int mode = g_mode;
    int r = load_edge_idx(ei, mode, e);
    int c = load_edge_idx(ei, mode, E_EDGES + e);
    if (r < 0 || r >= N_NODES || c < 0 || c >= N_NODES) return;
    int pos = atomicAdd(&g_cursor[c], 1);
    g_csr[pos] = r;
}

// ---- CSR gather-sum core: 4 threads per node, float4 lane p ----
__device__ __forceinline__ float4 csr_gather_sum(const float* __restrict__ src,
                                                 int node, int p) {
    float4 acc = ((const float4*)(src + node * HDIM))[p];  // self message (pre-scaled)
    int k   = g_off[node];
    int end = g_off[node + 1];
    for (; k + 1 < end; k += 2) {
        int r0 = g_csr[k], r1 = g_csr[k + 1];
        float4 a = ((const float4*)(src + r0 * HDIM))[p];
        float4 b = ((const float4*)(src + r1 * HDIM))[p];
        acc.x += a.x + b.x; acc.y += a.y + b.y;
        acc.z += a.z + b.z; acc.w += a.w + b.w;
    }
    if (k < end) {
        int r = g_csr[k];
        float4 a = ((const float4*)(src + r * HDIM))[p];
        acc.x += a.x; acc.y += a.y; acc.z += a.z; acc.w += a.w;
    }
    return acc;
}

// ---- launch 5: layer-1 aggregate + bias + relu + rescale -> z1s ----
__global__ void agg1_kernel(const float* __restrict__ b1) {
    int gid  = blockIdx.x * blockDim.x + threadIdx.x;
    int node = gid >> 2, p = gid & 3;
    if (node >= N_NODES) return;

    float4 acc  = csr_gather_sum(g_h, node, p);
    float  dinv = g_dinv[node];
    float4 bb   = ((const float4*)b1)[p];
    float4 z;
    z.x = fmaxf(dinv * acc.x + bb.x, 0.0f) * dinv;
    z.y = fmaxf(dinv * acc.y + bb.y, 0.0f) * dinv;
    z.z = fmaxf(dinv * acc.z + bb.z, 0.0f) * dinv;
    z.w = fmaxf(dinv * acc.w + bb.w, 0.0f) * dinv;
    ((float4*)(g_h2 + node * HDIM))[p] = z;
}

// ---- launch 6: layer-2 aggregate -> pre-GEMM features a = dinv*(sum) ----
__global__ void agg2_kernel() {
    int gid  = blockIdx.x * blockDim.x + threadIdx.x;
    int node = gid >> 2, p = gid & 3;
    if (node >= N_NODES) return;

    float4 acc  = csr_gather_sum(g_h2, node, p);
    float  dinv = g_dinv[node];
    acc.x *= dinv; acc.y *= dinv; acc.z *= dinv; acc.w *= dinv;
    ((float4*)(g_a + node * HDIM))[p] = acc;
}

// ---- launch 7: out = log_softmax(a @ W2 + b2) --- warp per row ----
__global__ void final_kernel(const float* __restrict__ W2, const float* __restrict__ b2,
                             float* __restrict__ out) {
    __shared__ float sW2[HDIM * FDIM];
    __shared__ float sb2[FDIM];
    for (int i = threadIdx.x; i < HDIM * FDIM; i += blockDim.x) sW2[i] = W2[i];
    for (int i = threadIdx.x; i < FDIM; i += blockDim.x)        sb2[i] = b2[i];
    __syncthreads();

    int warp = (blockIdx.x * blockDim.x + threadIdx.x) >> 5;
    int lane = threadIdx.x & 31;
    if (warp >= N_NODES) return;

    const float* ar = g_a + warp * HDIM;
    float a[HDIM];
#pragma unroll
    for (int k = 0; k < HDIM; k++) a[k] = ar[k];   // broadcast loads

    int c0 = lane * 4;
    float o0 = sb2[c0 + 0], o1 = sb2[c0 + 1], o2 = sb2[c0 + 2], o3 = sb2[c0 + 3];
#pragma unroll
    for (int k = 0; k < HDIM; k++) {
        float4 w = *(const float4*)&sW2[k * FDIM + c0];
        o0 += a[k] * w.x; o1 += a[k] * w.y; o2 += a[k] * w.z; o3 += a[k] * w.w;
    }

    float m = fmaxf(fmaxf(o0, o1), fmaxf(o2, o3));
#pragma unroll
    for (int off = 16; off > 0; off >>= 1)
        m = fmaxf(m, __shfl_xor_sync(0xFFFFFFFFu, m, off));

    float s = expf(o0 - m) + expf(o1 - m) + expf(o2 - m) + expf(o3 - m);
#pragma unroll
    for (int off = 16; off > 0; off >>= 1)
        s += __shfl_xor_sync(0xFFFFFFFFu, s, off);
    float lse = m + logf(s);

    float4 r = make_float4(o0 - lse, o1 - lse, o2 - lse, o3 - lse);
    *(float4*)(out + (size_t)warp * FDIM + c0) = r;
}

extern "C" void kernel_launch(void* const* d_in, const int* in_sizes, int n_in,
                              void* d_out, int out_size) {
    const float*        x  = nullptr;
    const unsigned int* ei = nullptr;
    const float*        W1 = nullptr;
    const float*        W2 = nullptr;
    const float*        b1 = nullptr;
    const float*        b2 = nullptr;

    for (int i = 0; i < n_in; i++) {
        long long sz = in_sizes[i];
        if (sz == 6400000LL || sz == 25600000LL)        x  = (const float*)d_in[i];
        else if (sz == 1200000LL || sz == 2400000LL ||
                 sz == 4800000LL || sz == 9600000LL)     ei = (const unsigned int*)d_in[i];
        else if (sz == 2048LL || sz == 8192LL) { if (!W1) W1 = (const float*)d_in[i];
                                                 else     W2 = (const float*)d_in[i]; }
        else if (sz == 16LL  || sz == 64LL)              b1 = (const float*)d_in[i];
        else if (sz == 128LL || sz == 512LL)             b2 = (const float*)d_in[i];
    }
    if (!x)  x  = (const float*)d_in[0];
    if (!ei) ei = (const unsigned int*)d_in[1];
    if (!W1) W1 = (const float*)d_in[2];
    if (!b1) b1 = (const float*)d_in[3];
    if (!W2) W2 = (const float*)d_in[4];
    if (!b2) b2 = (const float*)d_in[5];

    float* out = (float*)d_out;
    const int T = 256;

    detect_kernel<<<1, T>>>(ei);                                    // 0
    deg_kernel<<<(E_EDGES + T - 1) / T, T>>>(ei);                   // 1
    scan_kernel<<<1, 1024>>>();                                     // 2
    gemm1_kernel<<<(N_NODES * HDIM + T - 1) / T, T>>>(x, W1);       // 3
    fill_kernel<<<(E_EDGES + T - 1) / T, T>>>(ei);                  // 4
    agg1_kernel<<<(N_NODES * 4 + T - 1) / T, T>>>(b1);              // 5  <- ncu -s 5
    agg2_kernel<<<(N_NODES * 4 + T - 1) / T, T>>>();                // 6
    final_kernel<<<(N_NODES * 32 + T - 1) / T, T>>>(W2, b2, out);   // 7
}

// round 11
// speedup vs baseline: 1.2902x; 1.2902x over previous
#include <cuda_runtime.h>
#include <cuda_bf16.h>

#define N_NODES 50000
#define E_EDGES 600000
#define FDIM    128
#define HDIM    16

// scratch — device symbols referenced ONLY inside device code.
// Self-cleaning invariant: every kernel that consumes mutable state resets it.
__device__ int   g_mode;
__device__ float g_deg [N_NODES];            // 0 at rest
__device__ float g_dinv[N_NODES];
__device__ float g_h   [N_NODES * HDIM];     // h1s = dinv*(x@W1), then z1s
__device__ float g_acc1[N_NODES * HDIM];     // 0 at rest
__device__ float g_acc2[N_NODES * HDIM];     // 0 at rest

__device__ __forceinline__ int load_edge_idx(const unsigned int* __restrict__ ei,
                                             int mode, int pos) {
    if (mode == 1) return (int)ei[2 * pos];             // int64: low word
    unsigned int v = ei[pos];
    if (mode == 2) return (int)__int_as_float((int)v);  // float32-encoded
    return (int)v;                                      // int32
}

__device__ __forceinline__ void red_add_f4(float* addr, float4 v) {
    asm volatile("red.global.add.v4.f32 [%0], {%1,%2,%3,%4};"
                 :: "l"(addr), "f"(v.x), "f"(v.y), "f"(v.z), "f"(v.w) : "memory");
}

// ---- launch 0: detect edge dtype (1 block) ----
__global__ void detect_kernel(const unsigned int* __restrict__ w) {
    __shared__ int s_big, s_oddnz;
    if (threadIdx.x == 0) { s_big = 0; s_oddnz = 0; }
    __syncthreads();
    int big = 0, oddnz = 0;
    for (int k = threadIdx.x; k < 4096; k += blockDim.x) {
        unsigned int v = w[k];
        if (v >= 0x30000000u) big++;
        if ((k & 1) && v != 0u) oddnz++;
    }
    if (big)   atomicAdd(&s_big, big);
    if (oddnz) atomicAdd(&s_oddnz, oddnz);
    __syncthreads();
    if (threadIdx.x == 0) {
        if (s_big > 1024)      g_mode = 2;
        else if (s_oddnz == 0) g_mode = 1;
        else                   g_mode = 0;
    }
}

// ---- launch 1: degree count over targets (g_deg starts at 0) ----
__global__ void deg_kernel(const unsigned int* __restrict__ ei) {
    int e = blockIdx.x * blockDim.x + threadIdx.x;
    if (e < E_EDGES) {
        int c = load_edge_idx(ei, g_mode, E_EDGES + e);
        if (c >= 0 && c < N_NODES)
            atomicAdd(&g_deg[c], 1.0f);
    }
}

// ---- launch 2: h1s = dinv*(x@W1) --- 4 threads/row, 4 outputs each ----
// 4x less redundant L1 traffic than 16-threads/row; W1 tile via smem broadcast.
__global__ void gemm1_kernel(const float* __restrict__ x, const float* __restrict__ W1) {
    __shared__ float sW1[FDIM * HDIM];
    for (int i = threadIdx.x; i < FDIM * HDIM; i += blockDim.x)
        sW1[i] = W1[i];
    __syncthreads();

    int gid = blockIdx.x * blockDim.x + threadIdx.x;
    int row = gid >> 2;
    int jg  = (gid & 3) * 4;        // output column group base
    if (row >= N_NODES) return;

    float dinv = rsqrtf(g_deg[row] + 1.0f);   // +1 = self-loop

    const float4* xr = (const float4*)(x + (size_t)row * FDIM);
    float4 acc = make_float4(0.f, 0.f, 0.f, 0.f);
#pragma unroll
    for (int k4 = 0; k4 < FDIM / 4; k4++) {
        float4 xv = xr[k4];
        float4 w0 = *(const float4*)&sW1[(k4 * 4 + 0) * HDIM + jg];
        float4 w1 = *(const float4*)&sW1[(k4 * 4 + 1) * HDIM + jg];
        float4 w2 = *(const float4*)&sW1[(k4 * 4 + 2) * HDIM + jg];
        float4 w3 = *(const float4*)&sW1[(k4 * 4 + 3) * HDIM + jg];
        acc.x += xv.x * w0.x + xv.y * w1.x + xv.z * w2.x + xv.w * w3.x;
        acc.y += xv.x * w0.y + xv.y * w1.y + xv.z * w2.y + xv.w * w3.y;
        acc.z += xv.x * w0.z + xv.y * w1.z + xv.z * w2.z + xv.w * w3.z;
        acc.w += xv.x * w0.w + xv.y * w1.w + xv.z * w2.w + xv.w * w3.w;
    }
    acc.x *= dinv; acc.y *= dinv; acc.z *= dinv; acc.w *= dinv;
    *(float4*)(g_h + row * HDIM + jg) = acc;

    if (jg == 0) {
        g_dinv[row] = dinv;
        g_deg[row]  = 0.0f;    // self-clean for next replay
    }
}

// ---- launches 3 & 5: pure gather/scatter aggregation (no norm, no self-loops) ----
template <int PASS>
__global__ void agg_kernel(const unsigned int* __restrict__ ei) {
    int e = blockIdx.x * blockDim.x + threadIdx.x;
    if (e >= E_EDGES) return;

    float* __restrict__ acc = (PASS == 0) ? g_acc1 : g_acc2;

    int mode = g_mode;
    int r = load_edge_idx(ei, mode, e);
    int c = load_edge_idx(ei, mode, E_EDGES + e);
    if (r < 0 || r >= N_NODES || c < 0 || c >= N_NODES) return;

    const float4* hr = (const float4*)(g_h + r * HDIM);
    float*        ac = acc + c * HDIM;
#pragma unroll
    for (int p = 0; p < HDIM / 4; p++)
        red_add_f4(ac + p * 4, hr[p]);
}

// ---- launch 4: z1s = dinv * relu(dinv*(acc1 + h1s) + b1); reset acc1 ----
__global__ void relu_bias_kernel(const float* __restrict__ b1) {
    int idx = blockIdx.x * blockDim.x + threadIdx.x;
    if (idx >= N_NODES * HDIM) return;
    int j    = idx & 15;
    int node = idx >> 4;
    float dinv = g_dinv[node];
    float z = fmaxf(dinv * (g_acc1[idx] + g_h[idx]) + b1[j], 0.0f);
    g_h[idx]    = dinv * z;    // z1s for layer 2
    g_acc1[idx] = 0.0f;        // self-clean
}

// ---- launch 6: out = log_softmax(dinv*(acc2 + z1s) @ W2 + b2); reset acc2 ----
__global__ void final_kernel(const float* __restrict__ W2, const float* __restrict__ b2,
                             float* __restrict__ out) {
    __shared__ float sW2[HDIM * FDIM];
    __shared__ float sb2[FDIM];
    for (int i = threadIdx.x; i < HDIM * FDIM; i += blockDim.x) sW2[i] = W2[i];
    for (int i = threadIdx.x; i < FDIM; i += blockDim.x)        sb2[i] = b2[i];
    __syncthreads();

    int warp = (blockIdx.x * blockDim.x + threadIdx.x) >> 5;
    int lane = threadIdx.x & 31;
    if (warp >= N_NODES) return;

    float dinv = g_dinv[warp];
    const float* ar = g_acc2 + warp * HDIM;
    const float* zr = g_h    + warp * HDIM;
    float a[HDIM];
#pragma unroll
    for (int k = 0; k < HDIM; k++)
        a[k] = dinv * (ar[k] + zr[k]);   // broadcast loads within warp

    if (lane < 4)
        *(float4*)(g_acc2 + warp * HDIM + lane * 4) = make_float4(0.f, 0.f, 0.f, 0.f);

    int c0 = lane * 4;
    float o0 = sb2[c0 + 0], o1 = sb2[c0 + 1], o2 = sb2[c0 + 2], o3 = sb2[c0 + 3];
#pragma unroll
    for (int k = 0; k < HDIM; k++) {
        float4 w = *(const float4*)&sW2[k * FDIM + c0];
        o0 += a[k] * w.x; o1 += a[k] * w.y; o2 += a[k] * w.z; o3 += a[k] * w.w;
    }

    float m = fmaxf(fmaxf(o0, o1), fmaxf(o2, o3));
#pragma unroll
    for (int off = 16; off > 0; off >>= 1)
        m = fmaxf(m, __shfl_xor_sync(0xFFFFFFFFu, m, off));

    float s = expf(o0 - m) + expf(o1 - m) + expf(o2 - m) + expf(o3 - m);
#pragma unroll
    for (int off = 16; off > 0; off >>= 1)
        s += __shfl_xor_sync(0xFFFFFFFFu, s, off);
    float lse = m + logf(s);

    float4 r = make_float4(o0 - lse, o1 - lse, o2 - lse, o3 - lse);
    *(float4*)(out + (size_t)warp * FDIM + c0) = r;
}

extern "C" void kernel_launch(void* const* d_in, const int* in_sizes, int n_in,
                              void* d_out, int out_size) {
    const float*        x  = nullptr;
    const unsigned int* ei = nullptr;
    const float*        W1 = nullptr;
    const float*        W2 = nullptr;
    const float*        b1 = nullptr;
    const float*        b2 = nullptr;

    for (int i = 0; i < n_in; i++) {
        long long sz = in_sizes[i];
        if (sz == 6400000LL || sz == 25600000LL)        x  = (const float*)d_in[i];
        else if (sz == 1200000LL || sz == 2400000LL ||
                 sz == 4800000LL || sz == 9600000LL)     ei = (const unsigned int*)d_in[i];
        else if (sz == 2048LL || sz == 8192LL) { if (!W1) W1 = (const float*)d_in[i];
                                                 else     W2 = (const float*)d_in[i]; }
        else if (sz == 16LL  || sz == 64LL)              b1 = (const float*)d_in[i];
        else if (sz == 128LL || sz == 512LL)             b2 = (const float*)d_in[i];
    }
    if (!x)  x  = (const float*)d_in[0];
    if (!ei) ei = (const unsigned int*)d_in[1];
    if (!W1) W1 = (const float*)d_in[2];
    if (!b1) b1 = (const float*)d_in[3];
    if (!W2) W2 = (const float*)d_in[4];
    if (!b2) b2 = (const float*)d_in[5];

    float* out = (float*)d_out;
    const int T = 256;

    detect_kernel<<<1, T>>>(ei);                                    // 0
    deg_kernel<<<(E_EDGES + T - 1) / T, T>>>(ei);                   // 1
    gemm1_kernel<<<(N_NODES * 4 + T - 1) / T, T>>>(x, W1);          // 2
    agg_kernel<0><<<(E_EDGES + T - 1) / T, T>>>(ei);                // 3
    relu_bias_kernel<<<(N_NODES * HDIM + T - 1) / T, T>>>(b1);      // 4
    agg_kernel<1><<<(E_EDGES + T - 1) / T, T>>>(ei);                // 5  <- ncu -s 5
    final_kernel<<<(N_NODES * 32 + T - 1) / T, T>>>(W2, b2, out);   // 6
}